// round 16
// baseline (speedup 1.0000x reference)
#include <cuda_runtime.h>
#include <cuda_bf16.h>
#include <math.h>

#define B 64
#define S 4096
#define D 1024
#define NSPLIT 8
#define SPS (S / NSPLIT)   // 512
#define TILE 8
#define NTILE (SPS / TILE) // 64

#define KS 8               // split-K per operand

// ---------------- scratch (device globals: no allocation allowed) ----------
// g_q / g_lin are accumulated atomically by the GEMMs and re-zeroed by the
// finisher (zero-init at module load covers the first call).
__device__ float g_q[B * D];                 // 256 KB  q = query @ W_align^T
__device__ float g_lin[B * D];               // 256 KB  pre-tanh accumulator
__device__ float g_scores[B * S];            // 1 MB  masked raw scores
__device__ float g_pm[B * NSPLIT];
__device__ float g_pl[B * NSPLIT];
__device__ float g_pacc[B * NSPLIT * D];     // 2 MB  per-split unnormalized acc
__device__ float g_wc[B * D];
__device__ int   g_cnt[B];                   // flash per-batch counters
__device__ int   g_cnt2[D / 64];             // gemm3 per-d-tile counters

// ---------------- register-tiled skinny GEMM: out += A @ W^T ---------------
// Block: 64 b x 64 d tile over a k-chunk. 256 threads, each owns 4b x 4d.
// Epilogue: atomicAdd (REDG) into dense output — no partial buffers.
#define GBN 64
#define GBK 32

__global__ void __launch_bounds__(256) gemm_nt(
    const float* __restrict__ A0, const float* __restrict__ W0, float* __restrict__ out0,
    const float* __restrict__ A1, const float* __restrict__ W1, float* __restrict__ out1,
    int op_shift, int kchunk)
{
    const int which = blockIdx.y >> op_shift;
    const int slot  = blockIdx.y & ((1 << op_shift) - 1);
    const float* __restrict__ A = which ? A1 : A0;
    const float* __restrict__ W = which ? W1 : W0;
    float* __restrict__ outp = which ? out1 : out0;
    const int k0  = slot * kchunk;
    const int dn0 = blockIdx.x * GBN;

    __shared__ float As[GBK][B];     // [k][b]
    __shared__ float Ws[GBK][GBN];   // [k][d]

    const int tid = threadIdx.x;
    const int tx = tid & 15;         // d quad
    const int ty = tid >> 4;         // b quad

    float acc[4][4] = {};

    for (int bk = 0; bk < kchunk; bk += GBK) {
        #pragma unroll
        for (int r = 0; r < 2; r++) {
            int idx  = tid + r * 256;          // 0..511
            int pair = idx & 1;
            int bb   = (idx >> 1) & 63;
            int kq   = idx >> 7;               // 0..3
            int kb   = kq * 8 + pair * 4;
            float4 v = *reinterpret_cast<const float4*>(A + (size_t)bb * D + k0 + bk + kb);
            As[kb + 0][bb] = v.x; As[kb + 1][bb] = v.y;
            As[kb + 2][bb] = v.z; As[kb + 3][bb] = v.w;
        }
        #pragma unroll
        for (int r = 0; r < 2; r++) {
            int idx  = tid + r * 256;
            int pair = idx & 1;
            int dd   = (idx >> 1) & 63;
            int kq   = idx >> 7;
            int kb   = kq * 8 + pair * 4;
            float4 v = *reinterpret_cast<const float4*>(W + (size_t)(dn0 + dd) * D + k0 + bk + kb);
            Ws[kb + 0][dd] = v.x; Ws[kb + 1][dd] = v.y;
            Ws[kb + 2][dd] = v.z; Ws[kb + 3][dd] = v.w;
        }
        __syncthreads();
        #pragma unroll
        for (int kk = 0; kk < GBK; kk++) {
            float4 a = *reinterpret_cast<const float4*>(&As[kk][ty * 4]);
            float4 w = *reinterpret_cast<const float4*>(&Ws[kk][tx * 4]);
            acc[0][0] = fmaf(a.x, w.x, acc[0][0]); acc[0][1] = fmaf(a.x, w.y, acc[0][1]);
            acc[0][2] = fmaf(a.x, w.z, acc[0][2]); acc[0][3] = fmaf(a.x, w.w, acc[0][3]);
            acc[1][0] = fmaf(a.y, w.x, acc[1][0]); acc[1][1] = fmaf(a.y, w.y, acc[1][1]);
            acc[1][2] = fmaf(a.y, w.z, acc[1][2]); acc[1][3] = fmaf(a.y, w.w, acc[1][3]);
            acc[2][0] = fmaf(a.z, w.x, acc[2][0]); acc[2][1] = fmaf(a.z, w.y, acc[2][1]);
            acc[2][2] = fmaf(a.z, w.z, acc[2][2]); acc[2][3] = fmaf(a.z, w.w, acc[2][3]);
            acc[3][0] = fmaf(a.w, w.x, acc[3][0]); acc[3][1] = fmaf(a.w, w.y, acc[3][1]);
            acc[3][2] = fmaf(a.w, w.z, acc[3][2]); acc[3][3] = fmaf(a.w, w.w, acc[3][3]);
        }
        __syncthreads();
    }
    #pragma unroll
    for (int bi = 0; bi < 4; bi++) {
        float* dst = outp + (size_t)(ty * 4 + bi) * D + dn0 + tx * 4;
        atomicAdd(dst + 0, acc[bi][0]);
        atomicAdd(dst + 1, acc[bi][1]);
        atomicAdd(dst + 2, acc[bi][2]);
        atomicAdd(dst + 3, acc[bi][3]);
    }
}

// ---------------- gemm clone for launch 3: wc @ W_context^T + fused tanh ---
// DEDICATED kernel (separate codegen from the hot gemm_nt): grid (D/64, 8).
// Last block per d-tile applies tanh(g_lin) -> out and re-zeroes g_lin/g_q.
__global__ void __launch_bounds__(256) gemm_nt_tanh(
    const float* __restrict__ A, const float* __restrict__ W,
    float* __restrict__ outacc, float* __restrict__ final_out, int kchunk)
{
    const int slot = blockIdx.y;
    const int k0  = slot * kchunk;
    const int dn0 = blockIdx.x * GBN;

    __shared__ float As[GBK][B];
    __shared__ float Ws[GBK][GBN];
    __shared__ int   sh_last;

    const int tid = threadIdx.x;
    const int tx = tid & 15;
    const int ty = tid >> 4;

    float acc[4][4] = {};

    for (int bk = 0; bk < kchunk; bk += GBK) {
        #pragma unroll
        for (int r = 0; r < 2; r++) {
            int idx  = tid + r * 256;
            int pair = idx & 1;
            int bb   = (idx >> 1) & 63;
            int kq   = idx >> 7;
            int kb   = kq * 8 + pair * 4;
            float4 v = *reinterpret_cast<const float4*>(A + (size_t)bb * D + k0 + bk + kb);
            As[kb + 0][bb] = v.x; As[kb + 1][bb] = v.y;
            As[kb + 2][bb] = v.z; As[kb + 3][bb] = v.w;
        }
        #pragma unroll
        for (int r = 0; r < 2; r++) {
            int idx  = tid + r * 256;
            int pair = idx & 1;
            int dd   = (idx >> 1) & 63;
            int kq   = idx >> 7;
            int kb   = kq * 8 + pair * 4;
            float4 v = *reinterpret_cast<const float4*>(W + (size_t)(dn0 + dd) * D + k0 + bk + kb);
            Ws[kb + 0][dd] = v.x; Ws[kb + 1][dd] = v.y;
            Ws[kb + 2][dd] = v.z; Ws[kb + 3][dd] = v.w;
        }
        __syncthreads();
        #pragma unroll
        for (int kk = 0; kk < GBK; kk++) {
            float4 a = *reinterpret_cast<const float4*>(&As[kk][ty * 4]);
            float4 w = *reinterpret_cast<const float4*>(&Ws[kk][tx * 4]);
            acc[0][0] = fmaf(a.x, w.x, acc[0][0]); acc[0][1] = fmaf(a.x, w.y, acc[0][1]);
            acc[0][2] = fmaf(a.x, w.z, acc[0][2]); acc[0][3] = fmaf(a.x, w.w, acc[0][3]);
            acc[1][0] = fmaf(a.y, w.x, acc[1][0]); acc[1][1] = fmaf(a.y, w.y, acc[1][1]);
            acc[1][2] = fmaf(a.y, w.z, acc[1][2]); acc[1][3] = fmaf(a.y, w.w, acc[1][3]);
            acc[2][0] = fmaf(a.z, w.x, acc[2][0]); acc[2][1] = fmaf(a.z, w.y, acc[2][1]);
            acc[2][2] = fmaf(a.z, w.z, acc[2][2]); acc[2][3] = fmaf(a.z, w.w, acc[2][3]);
            acc[3][0] = fmaf(a.w, w.x, acc[3][0]); acc[3][1] = fmaf(a.w, w.y, acc[3][1]);
            acc[3][2] = fmaf(a.w, w.z, acc[3][2]); acc[3][3] = fmaf(a.w, w.w, acc[3][3]);
        }
        __syncthreads();
    }
    #pragma unroll
    for (int bi = 0; bi < 4; bi++) {
        float* dst = outacc + (size_t)(ty * 4 + bi) * D + dn0 + tx * 4;
        atomicAdd(dst + 0, acc[bi][0]);
        atomicAdd(dst + 1, acc[bi][1]);
        atomicAdd(dst + 2, acc[bi][2]);
        atomicAdd(dst + 3, acc[bi][3]);
    }

    // ---- last block per d-tile: tanh epilogue + scratch re-zero ----
    __threadfence();
    __syncthreads();
    if (tid == 0) {
        int prev = atomicAdd(&g_cnt2[blockIdx.x], 1);
        sh_last = (prev == (int)gridDim.y - 1);
    }
    __syncthreads();
    if (!sh_last) return;
    if (tid == 0) g_cnt2[blockIdx.x] = 0;    // reset for next graph replay

    // tile: 64 b-rows x 64 d-cols = 1024 float4; 4 per thread
    const float4 z = make_float4(0.f, 0.f, 0.f, 0.f);
    #pragma unroll
    for (int r = 0; r < 4; r++) {
        int idx = r * 256 + tid;             // 0..1023
        int bb  = idx >> 4;                  // b row
        int c4  = idx & 15;                  // float4 col within tile
        size_t off = (size_t)bb * (D / 4) + (dn0 >> 2) + c4;
        float4 v = reinterpret_cast<const float4*>(g_lin)[off];
        float4 rr = make_float4(tanhf(v.x), tanhf(v.y), tanhf(v.z), tanhf(v.w));
        reinterpret_cast<float4*>(final_out)[off] = rr;
        reinterpret_cast<float4*>(g_lin)[off] = z;   // re-zero for next replay
        reinterpret_cast<float4*>(g_q)[off]   = z;
    }
}

// ---------------- flash pass over context + fused per-batch combine --------
__global__ void __launch_bounds__(256, 4) attn_flash(
    const float* __restrict__ ctx, const int* __restrict__ mask,
    float* __restrict__ out_att, float* __restrict__ out_wc)
{
    const int split = blockIdx.x;
    const int b     = blockIdx.y;
    const int tid   = threadIdx.x;
    const int lane  = tid & 31;
    const int wid   = tid >> 5;

    __shared__ float sh_red[2][8][9];    // [parity][row][warp] (pad: conflict-free)
    __shared__ int   sh_last;

    // q slice for my 4 columns (dense, accumulated by gemm1)
    const float4 qr = *reinterpret_cast<const float4*>(g_q + b * D + tid * 4);

    float acc0 = 0.f, acc1 = 0.f, acc2 = 0.f, acc3 = 0.f;
    float m_run = -1e30f, l_run = 0.f;

    const float* __restrict__ cbase = ctx + (size_t)b * S * D + (size_t)split * SPS * D + tid * 4;
    const int*   __restrict__ mbase = mask + b * S + split * SPS;
    const int    sgbase = b * S + split * SPS;

    const bool h16 = (lane & 16) != 0;
    const bool h8  = (lane & 8)  != 0;
    const bool h4  = (lane & 4)  != 0;
    const int  myrow = lane & 7;

    for (int t = 0; t < NTILE; t++) {
        const int s0 = t * TILE;
        const float* tb = cbase + (size_t)s0 * D;
        const int par = t & 1;

        // ---- dot pass: f transient ----
        float p[TILE];
        #pragma unroll
        for (int j = 0; j < TILE; j++) {
            float4 f = *reinterpret_cast<const float4*>(tb + (size_t)j * D);
            p[j] = fmaf(f.x, qr.x, fmaf(f.y, qr.y, fmaf(f.z, qr.z, f.w * qr.w)));
        }

        // ---- butterfly fold: 8 rows x 32 lanes -> row (lane>>2) ----
        #pragma unroll
        for (int j = 0; j < 4; j++) {
            float send = h16 ? p[j] : p[j + 4];
            float recv = __shfl_xor_sync(0xffffffffu, send, 16);
            p[j] = (h16 ? p[j + 4] : p[j]) + recv;
        }
        #pragma unroll
        for (int j = 0; j < 2; j++) {
            float send = h8 ? p[j] : p[j + 2];
            float recv = __shfl_xor_sync(0xffffffffu, send, 8);
            p[j] = (h8 ? p[j + 2] : p[j]) + recv;
        }
        float pr;
        {
            float send = h4 ? p[0] : p[1];
            float recv = __shfl_xor_sync(0xffffffffu, send, 4);
            pr = (h4 ? p[1] : p[0]) + recv;
        }
        pr += __shfl_xor_sync(0xffffffffu, pr, 2);
        pr += __shfl_xor_sync(0xffffffffu, pr, 1);
        if ((lane & 3) == 0) sh_red[par][lane >> 2][wid] = pr;

        __syncthreads();   // single barrier per tile (smem double-buffered)

        // ---- cross-warp combine: my row's full dot + mask ----
        float v = 0.f;
        #pragma unroll
        for (int w = 0; w < 8; w++) v += sh_red[par][myrow][w];
        float a = (mbase[s0 + myrow] != 0) ? v : -1e30f;
        if (wid == 0 && lane < 8) g_scores[sgbase + s0 + lane] = a;

        // ---- tile max / weight / sum within 8-lane groups ----
        float m_tile = a;
        m_tile = fmaxf(m_tile, __shfl_xor_sync(0xffffffffu, m_tile, 1, 8));
        m_tile = fmaxf(m_tile, __shfl_xor_sync(0xffffffffu, m_tile, 2, 8));
        m_tile = fmaxf(m_tile, __shfl_xor_sync(0xffffffffu, m_tile, 4, 8));

        float w_own = (a > -1e29f) ? __expf(a - m_tile) : 0.f;   // ONE exp/thread
        float wsum = w_own;
        wsum += __shfl_xor_sync(0xffffffffu, wsum, 1, 8);
        wsum += __shfl_xor_sync(0xffffffffu, wsum, 2, 8);
        wsum += __shfl_xor_sync(0xffffffffu, wsum, 4, 8);

        // ---- online softmax update ----
        float new_m = fmaxf(m_run, m_tile);
        float scale = __expf(m_run - new_m);
        float tfac  = __expf(m_tile - new_m);
        m_run = new_m;
        l_run = fmaf(l_run, scale, wsum * tfac);
        acc0 *= scale; acc1 *= scale; acc2 *= scale; acc3 *= scale;
        float w_eff = w_own * tfac;

        // ---- weighted accumulate: re-load tile (L1 hit), w via shfl ----
        #pragma unroll
        for (int j = 0; j < TILE; j++) {
            float wj = __shfl_sync(0xffffffffu, w_eff, j, 8);
            float4 f = *reinterpret_cast<const float4*>(tb + (size_t)j * D);
            acc0 = fmaf(wj, f.x, acc0);
            acc1 = fmaf(wj, f.y, acc1);
            acc2 = fmaf(wj, f.z, acc2);
            acc3 = fmaf(wj, f.w, acc3);
        }
    }

    // ---- publish split partials ----
    if (tid == 0) {
        g_pm[b * NSPLIT + split] = m_run;
        g_pl[b * NSPLIT + split] = l_run;
    }
    float* pa = g_pacc + (size_t)(b * NSPLIT + split) * D + tid * 4;
    pa[0] = acc0; pa[1] = acc1; pa[2] = acc2; pa[3] = acc3;

    // ---- last-CTA-per-batch performs the combine ----
    __threadfence();
    __syncthreads();
    if (tid == 0) {
        int prev = atomicAdd(&g_cnt[b], 1);
        sh_last = (prev == NSPLIT - 1);
    }
    __syncthreads();
    if (!sh_last) return;
    if (tid == 0) g_cnt[b] = 0;              // reset for next graph replay

    float M = -1e30f;
    #pragma unroll
    for (int i = 0; i < NSPLIT; i++) M = fmaxf(M, g_pm[b * NSPLIT + i]);
    float fac[NSPLIT];
    float L = 0.f;
    #pragma unroll
    for (int i = 0; i < NSPLIT; i++) {
        fac[i] = __expf(g_pm[b * NSPLIT + i] - M);
        L = fmaf(g_pl[b * NSPLIT + i], fac[i], L);
    }
    const float invL = 1.f / L;

    // weight_context: 1024 cols = 256 float4, one per thread
    {
        const float4* pacc4 = reinterpret_cast<const float4*>(g_pacc) + (size_t)b * NSPLIT * (D / 4) + tid;
        float4 acc = make_float4(0.f, 0.f, 0.f, 0.f);
        #pragma unroll
        for (int i = 0; i < NSPLIT; i++) {
            float4 v = pacc4[(size_t)i * (D / 4)];
            acc.x = fmaf(fac[i], v.x, acc.x);
            acc.y = fmaf(fac[i], v.y, acc.y);
            acc.z = fmaf(fac[i], v.z, acc.z);
            acc.w = fmaf(fac[i], v.w, acc.w);
        }
        float4 wc = make_float4(acc.x * invL, acc.y * invL, acc.z * invL, acc.w * invL);
        reinterpret_cast<float4*>(g_wc)[b * (D / 4) + tid] = wc;
        reinterpret_cast<float4*>(out_wc)[b * (D / 4) + tid] = wc;
    }

    // attention: 4096 scores = 1024 float4, 4 per thread
    #pragma unroll
    for (int r = 0; r < 4; r++) {
        const int s4 = r * 256 + tid;
        float4 sc = reinterpret_cast<const float4*>(g_scores)[b * (S / 4) + s4];
        float4 rr = make_float4(__expf(sc.x - M) * invL, __expf(sc.y - M) * invL,
                                __expf(sc.z - M) * invL, __expf(sc.w - M) * invL);
        reinterpret_cast<float4*>(out_att)[b * (S / 4) + s4] = rr;
    }
}

// ---------------- launcher --------------------------------------------------
extern "C" void kernel_launch(void* const* d_in, const int* in_sizes, int n_in,
                              void* d_out, int out_size)
{
    const float* query     = (const float*)d_in[0];   // [B, D]
    const float* context   = (const float*)d_in[1];   // [B, S, D]
    const int*   ctx_mask  = (const int*)  d_in[2];   // [B, S]
    const float* W_align   = (const float*)d_in[3];   // [D, D]
    const float* W_context = (const float*)d_in[4];   // [D, D]
    const float* W_query   = (const float*)d_in[5];   // [D, D]

    float* out  = (float*)d_out;                      // [B, D]
    float* att  = out + B * D;                        // [B, S]
    float* owc  = att + B * S;                        // [B, D]

    float *pq = nullptr, *plin = nullptr, *pwc = nullptr;
    cudaGetSymbolAddress((void**)&pq,   g_q);
    cudaGetSymbolAddress((void**)&plin, g_lin);
    cudaGetSymbolAddress((void**)&pwc,  g_wc);

    // 1. q @ W_align^T -> g_q  AND  q @ W_query^T -> g_lin  (both input-only)
    gemm_nt<<<dim3(D / GBN, 2 * KS), 256>>>(query, W_align, pq,
                                            query, W_query, plin,
                                            3, 128);

    // 2. flash pass over context (1 GiB, read once) + fused per-batch combine
    attn_flash<<<dim3(NSPLIT, B), 256>>>(context, ctx_mask, att, owc);

    // 3. wc @ W_context^T -> g_lin, with fused last-block-per-d-tile tanh
    //    epilogue (writes out, re-zeroes g_lin/g_q). No separate tanh launch.
    gemm_nt_tanh<<<dim3(D / GBN, KS), 256>>>(pwc, W_context, plin, out, 128);
}

// round 17
// speedup vs baseline: 1.0220x; 1.0220x over previous
#include <cuda_runtime.h>
#include <cuda_bf16.h>
#include <math.h>

#define B 64
#define S 4096
#define D 1024
#define NSPLIT 8
#define SPS (S / NSPLIT)   // 512
#define TILE 8
#define NTILE (SPS / TILE) // 64

#define KS 16              // split-K per operand (deeper: shorter CTA critical path)

// ---------------- scratch (device globals: no allocation allowed) ----------
// g_q / g_lin are accumulated atomically by the GEMMs and re-zeroed by
// tanh_kernel after use (zero-init at module load covers the first call).
__device__ float g_q[B * D];                 // 256 KB  q = query @ W_align^T
__device__ float g_lin[B * D];               // 256 KB  pre-tanh accumulator
__device__ float g_scores[B * S];            // 1 MB  masked raw scores
__device__ float g_pm[B * NSPLIT];
__device__ float g_pl[B * NSPLIT];
__device__ float g_pacc[B * NSPLIT * D];     // 2 MB  per-split unnormalized acc
__device__ float g_wc[B * D];
__device__ int   g_cnt[B];                   // flash per-batch counters

// ---------------- register-tiled skinny GEMM: out += A @ W^T ---------------
// Block: 64 b x 64 d tile over a k-chunk. 256 threads, each owns 4b x 4d.
// Epilogue: atomicAdd (REDG) into dense output — no partial buffers.
#define GBN 64
#define GBK 32

__global__ void __launch_bounds__(256) gemm_nt(
    const float* __restrict__ A0, const float* __restrict__ W0, float* __restrict__ out0,
    const float* __restrict__ A1, const float* __restrict__ W1, float* __restrict__ out1,
    int op_shift, int kchunk)
{
    const int which = blockIdx.y >> op_shift;
    const int slot  = blockIdx.y & ((1 << op_shift) - 1);
    const float* __restrict__ A = which ? A1 : A0;
    const float* __restrict__ W = which ? W1 : W0;
    float* __restrict__ outp = which ? out1 : out0;
    const int k0  = slot * kchunk;
    const int dn0 = blockIdx.x * GBN;

    __shared__ float As[GBK][B];     // [k][b]
    __shared__ float Ws[GBK][GBN];   // [k][d]

    const int tid = threadIdx.x;
    const int tx = tid & 15;         // d quad
    const int ty = tid >> 4;         // b quad

    float acc[4][4] = {};

    for (int bk = 0; bk < kchunk; bk += GBK) {
        #pragma unroll
        for (int r = 0; r < 2; r++) {
            int idx  = tid + r * 256;          // 0..511
            int pair = idx & 1;
            int bb   = (idx >> 1) & 63;
            int kq   = idx >> 7;               // 0..3
            int kb   = kq * 8 + pair * 4;
            float4 v = *reinterpret_cast<const float4*>(A + (size_t)bb * D + k0 + bk + kb);
            As[kb + 0][bb] = v.x; As[kb + 1][bb] = v.y;
            As[kb + 2][bb] = v.z; As[kb + 3][bb] = v.w;
        }
        #pragma unroll
        for (int r = 0; r < 2; r++) {
            int idx  = tid + r * 256;
            int pair = idx & 1;
            int dd   = (idx >> 1) & 63;
            int kq   = idx >> 7;
            int kb   = kq * 8 + pair * 4;
            float4 v = *reinterpret_cast<const float4*>(W + (size_t)(dn0 + dd) * D + k0 + bk + kb);
            Ws[kb + 0][dd] = v.x; Ws[kb + 1][dd] = v.y;
            Ws[kb + 2][dd] = v.z; Ws[kb + 3][dd] = v.w;
        }
        __syncthreads();
        #pragma unroll
        for (int kk = 0; kk < GBK; kk++) {
            float4 a = *reinterpret_cast<const float4*>(&As[kk][ty * 4]);
            float4 w = *reinterpret_cast<const float4*>(&Ws[kk][tx * 4]);
            acc[0][0] = fmaf(a.x, w.x, acc[0][0]); acc[0][1] = fmaf(a.x, w.y, acc[0][1]);
            acc[0][2] = fmaf(a.x, w.z, acc[0][2]); acc[0][3] = fmaf(a.x, w.w, acc[0][3]);
            acc[1][0] = fmaf(a.y, w.x, acc[1][0]); acc[1][1] = fmaf(a.y, w.y, acc[1][1]);
            acc[1][2] = fmaf(a.y, w.z, acc[1][2]); acc[1][3] = fmaf(a.y, w.w, acc[1][3]);
            acc[2][0] = fmaf(a.z, w.x, acc[2][0]); acc[2][1] = fmaf(a.z, w.y, acc[2][1]);
            acc[2][2] = fmaf(a.z, w.z, acc[2][2]); acc[2][3] = fmaf(a.z, w.w, acc[2][3]);
            acc[3][0] = fmaf(a.w, w.x, acc[3][0]); acc[3][1] = fmaf(a.w, w.y, acc[3][1]);
            acc[3][2] = fmaf(a.w, w.z, acc[3][2]); acc[3][3] = fmaf(a.w, w.w, acc[3][3]);
        }
        __syncthreads();
    }
    #pragma unroll
    for (int bi = 0; bi < 4; bi++) {
        float* dst = outp + (size_t)(ty * 4 + bi) * D + dn0 + tx * 4;
        atomicAdd(dst + 0, acc[bi][0]);
        atomicAdd(dst + 1, acc[bi][1]);
        atomicAdd(dst + 2, acc[bi][2]);
        atomicAdd(dst + 3, acc[bi][3]);
    }
}

// ---------------- flash pass over context + fused per-batch combine --------
// TILE=8 (L1 re-read footprint 128KB < 228KB). Register-lean softmax:
// row-per-lane in width-8 shfl groups, ONE exp per thread.
__global__ void __launch_bounds__(256, 4) attn_flash(
    const float* __restrict__ ctx, const int* __restrict__ mask,
    float* __restrict__ out_att, float* __restrict__ out_wc)
{
    const int split = blockIdx.x;
    const int b     = blockIdx.y;
    const int tid   = threadIdx.x;
    const int lane  = tid & 31;
    const int wid   = tid >> 5;

    __shared__ float sh_red[2][8][9];    // [parity][row][warp] (pad: conflict-free)
    __shared__ int   sh_last;

    // q slice for my 4 columns (dense, accumulated by gemm1)
    const float4 qr = *reinterpret_cast<const float4*>(g_q + b * D + tid * 4);

    float acc0 = 0.f, acc1 = 0.f, acc2 = 0.f, acc3 = 0.f;
    float m_run = -1e30f, l_run = 0.f;

    const float* __restrict__ cbase = ctx + (size_t)b * S * D + (size_t)split * SPS * D + tid * 4;
    const int*   __restrict__ mbase = mask + b * S + split * SPS;
    const int    sgbase = b * S + split * SPS;

    const bool h16 = (lane & 16) != 0;
    const bool h8  = (lane & 8)  != 0;
    const bool h4  = (lane & 4)  != 0;
    const int  myrow = lane & 7;

    for (int t = 0; t < NTILE; t++) {
        const int s0 = t * TILE;
        const float* tb = cbase + (size_t)s0 * D;
        const int par = t & 1;

        // ---- dot pass: f transient ----
        float p[TILE];
        #pragma unroll
        for (int j = 0; j < TILE; j++) {
            float4 f = *reinterpret_cast<const float4*>(tb + (size_t)j * D);
            p[j] = fmaf(f.x, qr.x, fmaf(f.y, qr.y, fmaf(f.z, qr.z, f.w * qr.w)));
        }

        // ---- butterfly fold: 8 rows x 32 lanes -> row (lane>>2) ----
        #pragma unroll
        for (int j = 0; j < 4; j++) {
            float send = h16 ? p[j] : p[j + 4];
            float recv = __shfl_xor_sync(0xffffffffu, send, 16);
            p[j] = (h16 ? p[j + 4] : p[j]) + recv;
        }
        #pragma unroll
        for (int j = 0; j < 2; j++) {
            float send = h8 ? p[j] : p[j + 2];
            float recv = __shfl_xor_sync(0xffffffffu, send, 8);
            p[j] = (h8 ? p[j + 2] : p[j]) + recv;
        }
        float pr;
        {
            float send = h4 ? p[0] : p[1];
            float recv = __shfl_xor_sync(0xffffffffu, send, 4);
            pr = (h4 ? p[1] : p[0]) + recv;
        }
        pr += __shfl_xor_sync(0xffffffffu, pr, 2);
        pr += __shfl_xor_sync(0xffffffffu, pr, 1);
        if ((lane & 3) == 0) sh_red[par][lane >> 2][wid] = pr;

        __syncthreads();   // single barrier per tile (smem double-buffered)

        // ---- cross-warp combine: my row's full dot + mask ----
        float v = 0.f;
        #pragma unroll
        for (int w = 0; w < 8; w++) v += sh_red[par][myrow][w];
        float a = (mbase[s0 + myrow] != 0) ? v : -1e30f;
        if (wid == 0 && lane < 8) g_scores[sgbase + s0 + lane] = a;

        // ---- tile max / weight / sum within 8-lane groups ----
        float m_tile = a;
        m_tile = fmaxf(m_tile, __shfl_xor_sync(0xffffffffu, m_tile, 1, 8));
        m_tile = fmaxf(m_tile, __shfl_xor_sync(0xffffffffu, m_tile, 2, 8));
        m_tile = fmaxf(m_tile, __shfl_xor_sync(0xffffffffu, m_tile, 4, 8));

        float w_own = (a > -1e29f) ? __expf(a - m_tile) : 0.f;   // ONE exp/thread
        float wsum = w_own;
        wsum += __shfl_xor_sync(0xffffffffu, wsum, 1, 8);
        wsum += __shfl_xor_sync(0xffffffffu, wsum, 2, 8);
        wsum += __shfl_xor_sync(0xffffffffu, wsum, 4, 8);

        // ---- online softmax update ----
        float new_m = fmaxf(m_run, m_tile);
        float scale = __expf(m_run - new_m);
        float tfac  = __expf(m_tile - new_m);
        m_run = new_m;
        l_run = fmaf(l_run, scale, wsum * tfac);
        acc0 *= scale; acc1 *= scale; acc2 *= scale; acc3 *= scale;
        float w_eff = w_own * tfac;

        // ---- weighted accumulate: re-load tile (L1 hit), w via shfl ----
        #pragma unroll
        for (int j = 0; j < TILE; j++) {
            float wj = __shfl_sync(0xffffffffu, w_eff, j, 8);
            float4 f = *reinterpret_cast<const float4*>(tb + (size_t)j * D);
            acc0 = fmaf(wj, f.x, acc0);
            acc1 = fmaf(wj, f.y, acc1);
            acc2 = fmaf(wj, f.z, acc2);
            acc3 = fmaf(wj, f.w, acc3);
        }
    }

    // ---- publish split partials ----
    if (tid == 0) {
        g_pm[b * NSPLIT + split] = m_run;
        g_pl[b * NSPLIT + split] = l_run;
    }
    float* pa = g_pacc + (size_t)(b * NSPLIT + split) * D + tid * 4;
    pa[0] = acc0; pa[1] = acc1; pa[2] = acc2; pa[3] = acc3;

    // ---- last-CTA-per-batch performs the combine ----
    __threadfence();
    __syncthreads();
    if (tid == 0) {
        int prev = atomicAdd(&g_cnt[b], 1);
        sh_last = (prev == NSPLIT - 1);
    }
    __syncthreads();
    if (!sh_last) return;
    if (tid == 0) g_cnt[b] = 0;              // reset for next graph replay

    float M = -1e30f;
    #pragma unroll
    for (int i = 0; i < NSPLIT; i++) M = fmaxf(M, g_pm[b * NSPLIT + i]);
    float fac[NSPLIT];
    float L = 0.f;
    #pragma unroll
    for (int i = 0; i < NSPLIT; i++) {
        fac[i] = __expf(g_pm[b * NSPLIT + i] - M);
        L = fmaf(g_pl[b * NSPLIT + i], fac[i], L);
    }
    const float invL = 1.f / L;

    // weight_context: 1024 cols = 256 float4, one per thread
    {
        const float4* pacc4 = reinterpret_cast<const float4*>(g_pacc) + (size_t)b * NSPLIT * (D / 4) + tid;
        float4 acc = make_float4(0.f, 0.f, 0.f, 0.f);
        #pragma unroll
        for (int i = 0; i < NSPLIT; i++) {
            float4 v = pacc4[(size_t)i * (D / 4)];
            acc.x = fmaf(fac[i], v.x, acc.x);
            acc.y = fmaf(fac[i], v.y, acc.y);
            acc.z = fmaf(fac[i], v.z, acc.z);
            acc.w = fmaf(fac[i], v.w, acc.w);
        }
        float4 wc = make_float4(acc.x * invL, acc.y * invL, acc.z * invL, acc.w * invL);
        reinterpret_cast<float4*>(g_wc)[b * (D / 4) + tid] = wc;
        reinterpret_cast<float4*>(out_wc)[b * (D / 4) + tid] = wc;
    }

    // attention: 4096 scores = 1024 float4, 4 per thread
    #pragma unroll
    for (int r = 0; r < 4; r++) {
        const int s4 = r * 256 + tid;
        float4 sc = reinterpret_cast<const float4*>(g_scores)[b * (S / 4) + s4];
        float4 rr = make_float4(__expf(sc.x - M) * invL, __expf(sc.y - M) * invL,
                                __expf(sc.z - M) * invL, __expf(sc.w - M) * invL);
        reinterpret_cast<float4*>(out_att)[b * (S / 4) + s4] = rr;
    }
}

// ---------------- tanh epilogue + scratch re-zero for next replay ----------
__global__ void __launch_bounds__(256) tanh_kernel(float* __restrict__ out) {
    const int i = blockIdx.x * blockDim.x + threadIdx.x;   // float4 idx, 16384
    float4* lin4 = reinterpret_cast<float4*>(g_lin);
    float4* q4   = reinterpret_cast<float4*>(g_q);
    float4 v = lin4[i];
    float4 r = make_float4(tanhf(v.x), tanhf(v.y), tanhf(v.z), tanhf(v.w));
    reinterpret_cast<float4*>(out)[i] = r;
    float4 z = make_float4(0.f, 0.f, 0.f, 0.f);
    lin4[i] = z;       // re-zero accumulators for the next graph replay
    q4[i]   = z;
}

// ---------------- launcher --------------------------------------------------
extern "C" void kernel_launch(void* const* d_in, const int* in_sizes, int n_in,
                              void* d_out, int out_size)
{
    const float* query     = (const float*)d_in[0];   // [B, D]
    const float* context   = (const float*)d_in[1];   // [B, S, D]
    const int*   ctx_mask  = (const int*)  d_in[2];   // [B, S]
    const float* W_align   = (const float*)d_in[3];   // [D, D]
    const float* W_context = (const float*)d_in[4];   // [D, D]
    const float* W_query   = (const float*)d_in[5];   // [D, D]

    float* out  = (float*)d_out;                      // [B, D]
    float* att  = out + B * D;                        // [B, S]
    float* owc  = att + B * S;                        // [B, D]

    float *pq = nullptr, *plin = nullptr, *pwc = nullptr;
    cudaGetSymbolAddress((void**)&pq,   g_q);
    cudaGetSymbolAddress((void**)&plin, g_lin);
    cudaGetSymbolAddress((void**)&pwc,  g_wc);

    // 1. q @ W_align^T -> g_q  AND  q @ W_query^T -> g_lin (both input-only).
    //    Split-K 16 per operand: 512 CTAs, 2 k-chunks/CTA (half the critical path).
    gemm_nt<<<dim3(D / GBN, 2 * KS), 256>>>(query, W_align, pq,
                                            query, W_query, plin,
                                            4, D / KS);

    // 2. flash pass over context (1 GiB, read once) + fused per-batch combine
    attn_flash<<<dim3(NSPLIT, B), 256>>>(context, ctx_mask, att, owc);

    // 3. wc @ W_context^T -> g_lin (split-K 16: 256 CTAs, short critical path)
    gemm_nt<<<dim3(D / GBN, KS), 256>>>(pwc, W_context, plin,
                                        pwc, W_context, plin,   // unused op1
                                        4, D / KS);

    // 4. out = tanh(g_lin); re-zero g_lin/g_q for the next replay
    tanh_kernel<<<64, 256>>>(out);
}